// round 5
// baseline (speedup 1.0000x reference)
#include <cuda_runtime.h>
#include <cuda_bf16.h>
#include <math.h>
#include <stdint.h>

#define T_TOK 8192
#define H 1024
#define E 8
#define CAP 1024   // capacity = T/E

// ---------------- scratch (no allocations allowed) ----------------
__device__ int   g_expert_idx[T_TOK];
__device__ float g_gate[T_TOK];
__device__ int   g_slot_token[E * CAP];   // token id per (expert, slot), -1 if empty
__device__ __align__(256) __nv_bfloat16 g_Whi[E * H * H];   // 16 MB
__device__ __align__(256) __nv_bfloat16 g_Wlo[E * H * H];   // 16 MB
__device__ __align__(256) __nv_bfloat16 g_Ahi[T_TOK * H];   // 16 MB (gathered per-slot x)
__device__ __align__(256) __nv_bfloat16 g_Alo[T_TOK * H];   // 16 MB

// ---------------- kernel 1: routing ----------------
__global__ void route_kernel(const float* __restrict__ x,
                             const float* __restrict__ wg) {
    __shared__ float s_wg[H * E];
    for (int i = threadIdx.x; i < H * E; i += blockDim.x) s_wg[i] = wg[i];
    __syncthreads();

    int warp = (blockIdx.x * blockDim.x + threadIdx.x) >> 5;
    int lane = threadIdx.x & 31;
    if (warp >= T_TOK) return;

    const float* xp = x + (size_t)warp * H;
    float acc[E];
#pragma unroll
    for (int e = 0; e < E; e++) acc[e] = 0.f;
    for (int k = lane; k < H; k += 32) {
        float xv = xp[k];
        const float* w = s_wg + k * E;
#pragma unroll
        for (int e = 0; e < E; e++) acc[e] = fmaf(xv, w[e], acc[e]);
    }
#pragma unroll
    for (int e = 0; e < E; e++) {
#pragma unroll
        for (int o = 16; o > 0; o >>= 1)
            acc[e] += __shfl_down_sync(0xffffffffu, acc[e], o);
    }
    if (lane == 0) {
        float m = acc[0]; int bi = 0;
#pragma unroll
        for (int e = 1; e < E; e++)
            if (acc[e] > m) { m = acc[e]; bi = e; }
        float s = 0.f;
#pragma unroll
        for (int e = 0; e < E; e++) s += expf(acc[e] - m);
        g_expert_idx[warp] = bi;
        g_gate[warp]       = 1.f / s;
    }
}

// ---------------- kernel 2: order-preserving scan (warp-shuffle) ----------------
__global__ void scan_kernel() {
    __shared__ unsigned long long w0[32], w1[32];
    const int tid = threadIdx.x;
    const int lane = tid & 31, wid = tid >> 5;

    const int base = tid * 8;
    int eidx[8];
    unsigned long long c0 = 0ULL, c1 = 0ULL;
#pragma unroll
    for (int j = 0; j < 8; j++) {
        int e = g_expert_idx[base + j];
        eidx[j] = e;
        if (e < 4) c0 += 1ULL << (16 * e);
        else       c1 += 1ULL << (16 * (e - 4));
    }
    // warp inclusive scan
    unsigned long long s0 = c0, s1 = c1;
#pragma unroll
    for (int d = 1; d < 32; d <<= 1) {
        unsigned long long t0 = __shfl_up_sync(0xffffffffu, s0, d);
        unsigned long long t1 = __shfl_up_sync(0xffffffffu, s1, d);
        if (lane >= d) { s0 += t0; s1 += t1; }
    }
    if (lane == 31) { w0[wid] = s0; w1[wid] = s1; }

    // init slot table while waiting
    for (int i = tid; i < E * CAP; i += 1024) g_slot_token[i] = -1;
    __syncthreads();
    if (wid == 0) {
        unsigned long long v0 = w0[lane], v1 = w1[lane];
#pragma unroll
        for (int d = 1; d < 32; d <<= 1) {
            unsigned long long t0 = __shfl_up_sync(0xffffffffu, v0, d);
            unsigned long long t1 = __shfl_up_sync(0xffffffffu, v1, d);
            if (lane >= d) { v0 += t0; v1 += t1; }
        }
        w0[lane] = v0; w1[lane] = v1;
    }
    __syncthreads();
    unsigned long long o0 = s0 - c0 + (wid > 0 ? w0[wid - 1] : 0ULL);
    unsigned long long o1 = s1 - c1 + (wid > 0 ? w1[wid - 1] : 0ULL);

    int off[E];
#pragma unroll
    for (int e = 0; e < 4; e++) {
        off[e]     = (int)((o0 >> (16 * e)) & 0xFFFFULL);
        off[e + 4] = (int)((o1 >> (16 * e)) & 0xFFFFULL);
    }
#pragma unroll
    for (int j = 0; j < 8; j++) {
        int t = base + j;
        int e = eidx[j];
        int p = 0;
#pragma unroll
        for (int q = 0; q < E; q++)
            if (e == q) { p = off[q]; off[q] = p + 1; }
        if (p < CAP) g_slot_token[e * CAP + p] = t;
    }
}

// ---------------- kernel 3: zero output ----------------
__global__ void zero_kernel(float4* __restrict__ out) {
    size_t i = (size_t)blockIdx.x * blockDim.x + threadIdx.x;
    out[i] = make_float4(0.f, 0.f, 0.f, 0.f);
}

// ---------------- hi/lo bf16 split helpers ----------------
__device__ __forceinline__ void split8(const float4 a, const float4 b,
                                       uint4& hi, uint4& lo) {
    float v[8] = {a.x, a.y, a.z, a.w, b.x, b.y, b.z, b.w};
    __nv_bfloat16 h[8], l[8];
#pragma unroll
    for (int i = 0; i < 8; i++) {
        h[i] = __float2bfloat16(v[i]);
        l[i] = __float2bfloat16(v[i] - __bfloat162float(h[i]));
    }
    hi = *(uint4*)h;
    lo = *(uint4*)l;
}

// ---------------- kernel 4: convert W -> bf16 hi/lo ----------------
__global__ void convW_kernel(const float* __restrict__ W) {
    size_t i = ((size_t)blockIdx.x * blockDim.x + threadIdx.x) * 8;
    float4 a = *(const float4*)(W + i);
    float4 b = *(const float4*)(W + i + 4);
    uint4 hi, lo;
    split8(a, b, hi, lo);
    *(uint4*)(g_Whi + i) = hi;
    *(uint4*)(g_Wlo + i) = lo;
}

// ---------------- kernel 5: gather + convert x -> per-slot bf16 hi/lo ----------------
__global__ void convA_kernel(const float* __restrict__ x) {
    int r = blockIdx.x;                 // global slot row 0..8191
    int tok = g_slot_token[r];
    size_t base = (size_t)r * H + threadIdx.x * 8;   // 128 threads * 8 = 1024
    if (tok < 0) {
        uint4 z = make_uint4(0, 0, 0, 0);
        *(uint4*)(g_Ahi + base) = z;
        *(uint4*)(g_Alo + base) = z;
        return;
    }
    const float* xr = x + (size_t)tok * H + threadIdx.x * 8;
    float4 a = *(const float4*)xr;
    float4 b = *(const float4*)(xr + 4);
    uint4 hi, lo;
    split8(a, b, hi, lo);
    *(uint4*)(g_Ahi + base) = hi;
    *(uint4*)(g_Alo + base) = lo;
}

// ---------------- kernel 6: GEMM via mma.sync bf16, cp.async pipeline ----------------
#define BM 128
#define BN 128
#define BK 32
#define KITER (H / BK)            // 32
#define LDS_STRIDE 40             // bf16 elems per smem row (32 data + 8 pad) = 80B
#define PLANE_B (BM * LDS_STRIDE * 2)   // 10240 bytes per plane
#define STAGE_B (4 * PLANE_B)           // 40960 bytes
#define SMEM_TOK 512
#define GEMM_SMEM (SMEM_TOK + 2 * STAGE_B)  // 82432 bytes

__device__ __forceinline__ uint32_t smem_u32(const void* p) {
    uint32_t a;
    asm("{ .reg .u64 t; cvta.to.shared.u64 t, %1; cvt.u32.u64 %0, t; }" : "=r"(a) : "l"(p));
    return a;
}
__device__ __forceinline__ void cpasync16(uint32_t dst, const void* src) {
    asm volatile("cp.async.cg.shared.global [%0], [%1], 16;" :: "r"(dst), "l"(src));
}
__device__ __forceinline__ void ldsm4(uint32_t& r0, uint32_t& r1, uint32_t& r2, uint32_t& r3,
                                      uint32_t addr) {
    asm volatile("ldmatrix.sync.aligned.m8n8.x4.shared.b16 {%0,%1,%2,%3}, [%4];"
                 : "=r"(r0), "=r"(r1), "=r"(r2), "=r"(r3) : "r"(addr));
}
__device__ __forceinline__ void mma16816(float* d, const uint32_t* a, uint32_t b0, uint32_t b1) {
    asm volatile("mma.sync.aligned.m16n8k16.row.col.f32.bf16.bf16.f32 "
                 "{%0,%1,%2,%3}, {%4,%5,%6,%7}, {%8,%9}, {%0,%1,%2,%3};"
                 : "+f"(d[0]), "+f"(d[1]), "+f"(d[2]), "+f"(d[3])
                 : "r"(a[0]), "r"(a[1]), "r"(a[2]), "r"(a[3]), "r"(b0), "r"(b1));
}

__device__ __forceinline__ void compute_chunk(uint32_t ab, int mrow, int nrow, int lane,
                                              float D[4][4][4]) {
#pragma unroll
    for (int ks = 0; ks < 2; ks++) {
        const uint32_t colb = (uint32_t)((ks * 16 + (lane >> 4) * 8) * 2);
        uint32_t ahi[4][4], alo[4][4], bh[2][4], bl[2][4];
#pragma unroll
        for (int mt = 0; mt < 4; mt++) {
            uint32_t ad = ab + (mrow + mt * 16) * (LDS_STRIDE * 2) + colb;
            ldsm4(ahi[mt][0], ahi[mt][1], ahi[mt][2], ahi[mt][3], ad);
            ldsm4(alo[mt][0], alo[mt][1], alo[mt][2], alo[mt][3], ad + PLANE_B);
        }
#pragma unroll
        for (int np = 0; np < 2; np++) {
            uint32_t bd = ab + 2 * PLANE_B + (nrow + np * 16) * (LDS_STRIDE * 2) + colb;
            ldsm4(bh[np][0], bh[np][1], bh[np][2], bh[np][3], bd);
            ldsm4(bl[np][0], bl[np][1], bl[np][2], bl[np][3], bd + PLANE_B);
        }
#pragma unroll
        for (int mt = 0; mt < 4; mt++)
#pragma unroll
            for (int nt = 0; nt < 4; nt++) {
                int np = nt >> 1, od = nt & 1;
                mma16816(D[mt][nt], ahi[mt], bh[np][od], bh[np][2 + od]);
                mma16816(D[mt][nt], ahi[mt], bl[np][od], bl[np][2 + od]);
                mma16816(D[mt][nt], alo[mt], bh[np][od], bh[np][2 + od]);
            }
    }
}

__global__ void __launch_bounds__(256, 2)
moe_gemm(const float* __restrict__ bias, float* __restrict__ out) {
    extern __shared__ char smem[];
    int* s_tok = (int*)smem;
    const uint32_t sbase = smem_u32(smem) + SMEM_TOK;

    const int tid  = threadIdx.x;
    const int lane = tid & 31;
    const int wid  = tid >> 5;
    const int bm = blockIdx.y * BM;       // global slot row base
    const int bn = blockIdx.x * BN;       // output feature base
    const int e  = bm >> 10;              // expert

    if (tid < BM) s_tok[tid] = g_slot_token[bm + tid];

    // ---- cp.async mapping: each thread = 1 row-half (32B) per plane ----
    const int crow = tid >> 1;
    const int cseg = (tid & 1) * 2;       // 16B segments cseg, cseg+1
    const __nv_bfloat16* sAhi = g_Ahi + (size_t)(bm + crow) * H + cseg * 8;
    const __nv_bfloat16* sAlo = g_Alo + (size_t)(bm + crow) * H + cseg * 8;
    const __nv_bfloat16* sBhi = g_Whi + ((size_t)e * H + bn + crow) * H + cseg * 8;
    const __nv_bfloat16* sBlo = g_Wlo + ((size_t)e * H + bn + crow) * H + cseg * 8;
    const uint32_t dstb = (uint32_t)(crow * (LDS_STRIDE * 2) + cseg * 16);

#define ISSUE_STAGE(stg, kc) do { \
        uint32_t db = sbase + (stg) * STAGE_B + dstb; \
        int ko = (kc) * BK; \
        cpasync16(db,                        sAhi + ko);      \
        cpasync16(db + 16,                   sAhi + ko + 8);  \
        cpasync16(db + PLANE_B,              sAlo + ko);      \
        cpasync16(db + PLANE_B + 16,         sAlo + ko + 8);  \
        cpasync16(db + 2 * PLANE_B,          sBhi + ko);      \
        cpasync16(db + 2 * PLANE_B + 16,     sBhi + ko + 8);  \
        cpasync16(db + 3 * PLANE_B,          sBlo + ko);      \
        cpasync16(db + 3 * PLANE_B + 16,     sBlo + ko + 8);  \
        asm volatile("cp.async.commit_group;" ::: "memory"); \
    } while (0)

    float D[4][4][4];
#pragma unroll
    for (int mt = 0; mt < 4; mt++)
#pragma unroll
        for (int nt = 0; nt < 4; nt++)
#pragma unroll
            for (int r = 0; r < 4; r++) D[mt][nt][r] = 0.f;

    const int mrow = (wid >> 2) * 64 + (lane & 15);
    const int nrow = (wid & 3) * 32 + (lane & 15);

    ISSUE_STAGE(0, 0);
    for (int kc = 0; kc < KITER; kc++) {
        if (kc + 1 < KITER) {
            ISSUE_STAGE((kc + 1) & 1, kc + 1);
            asm volatile("cp.async.wait_group 1;" ::: "memory");
        } else {
            asm volatile("cp.async.wait_group 0;" ::: "memory");
        }
        __syncthreads();
        compute_chunk(sbase + (kc & 1) * STAGE_B, mrow, nrow, lane, D);
        __syncthreads();
    }

    // ---- epilogue: gate * (D + bias) scattered to token rows ----
    const int wm = (wid >> 2) * 64;
    const int wn = (wid & 3) * 32;
#pragma unroll
    for (int mt = 0; mt < 4; mt++) {
#pragma unroll
        for (int half = 0; half < 2; half++) {
            int r = wm + mt * 16 + (lane >> 2) + half * 8;
            int tok = s_tok[r];
            if (tok < 0) continue;
            float g = g_gate[tok];
            float* orow = out + (size_t)tok * H + bn + wn;
#pragma unroll
            for (int nt = 0; nt < 4; nt++) {
                int c = nt * 8 + (lane & 3) * 2;
                float2 bb = *(const float2*)(bias + (size_t)e * H + bn + wn + c);
                float2 v;
                v.x = g * (D[mt][nt][half * 2 + 0] + bb.x);
                v.y = g * (D[mt][nt][half * 2 + 1] + bb.y);
                *(float2*)(orow + c) = v;
            }
        }
    }
}

extern "C" void kernel_launch(void* const* d_in, const int* in_sizes, int n_in,
                              void* d_out, int out_size) {
    const float* x  = (const float*)d_in[0];   // [T, H]
    const float* wg = (const float*)d_in[1];   // [H, E]
    const float* W  = (const float*)d_in[2];   // [E, H, H]
    const float* b  = (const float*)d_in[3];   // [E, H]
    float* out = (float*)d_out;                // [T, H]

    cudaFuncSetAttribute(moe_gemm, cudaFuncAttributeMaxDynamicSharedMemorySize, GEMM_SMEM);

    route_kernel<<<T_TOK / 8, 256>>>(x, wg);
    scan_kernel<<<1, 1024>>>();
    convW_kernel<<<(E * H * H / 8) / 256, 256>>>(W);
    zero_kernel<<<(T_TOK * H / 4) / 256, 256>>>((float4*)out);
    convA_kernel<<<T_TOK, 128>>>(x);
    dim3 grid(H / BN, T_TOK / BM);             // (8, 64)
    moe_gemm<<<grid, 256, GEMM_SMEM>>>(b, out);
}

// round 7
// speedup vs baseline: 1.1715x; 1.1715x over previous
#include <cuda_runtime.h>
#include <cuda_bf16.h>
#include <math.h>
#include <stdint.h>

#define T_TOK 8192
#define H 1024
#define E 8
#define CAP 1024   // capacity = T/E

// ---------------- scratch (no allocations allowed) ----------------
__device__ int   g_expert_idx[T_TOK];
__device__ float g_gate[T_TOK];
__device__ int   g_slot_token[E * CAP];   // token id per (expert, slot), -1 if empty
__device__ __align__(256) __nv_bfloat16 g_Whi[E * H * H];   // 16 MB
__device__ __align__(256) __nv_bfloat16 g_Wlo[E * H * H];   // 16 MB
__device__ __align__(256) __nv_bfloat16 g_Ahi[T_TOK * H];   // 16 MB (gathered per-slot x)
__device__ __align__(256) __nv_bfloat16 g_Alo[T_TOK * H];   // 16 MB

// ---------------- kernel 1: routing ----------------
__global__ void route_kernel(const float* __restrict__ x,
                             const float* __restrict__ wg) {
    __shared__ float s_wg[H * E];
    for (int i = threadIdx.x; i < H * E; i += blockDim.x) s_wg[i] = wg[i];
    __syncthreads();

    int warp = (blockIdx.x * blockDim.x + threadIdx.x) >> 5;
    int lane = threadIdx.x & 31;
    if (warp >= T_TOK) return;

    const float* xp = x + (size_t)warp * H;
    float acc[E];
#pragma unroll
    for (int e = 0; e < E; e++) acc[e] = 0.f;
    for (int k = lane; k < H; k += 32) {
        float xv = xp[k];
        const float* w = s_wg + k * E;
#pragma unroll
        for (int e = 0; e < E; e++) acc[e] = fmaf(xv, w[e], acc[e]);
    }
#pragma unroll
    for (int e = 0; e < E; e++) {
#pragma unroll
        for (int o = 16; o > 0; o >>= 1)
            acc[e] += __shfl_down_sync(0xffffffffu, acc[e], o);
    }
    if (lane == 0) {
        float m = acc[0]; int bi = 0;
#pragma unroll
        for (int e = 1; e < E; e++)
            if (acc[e] > m) { m = acc[e]; bi = e; }
        float s = 0.f;
#pragma unroll
        for (int e = 0; e < E; e++) s += expf(acc[e] - m);
        g_expert_idx[warp] = bi;
        g_gate[warp]       = 1.f / s;
    }
}

// ---------------- kernel 2: order-preserving scan (warp-shuffle) ----------------
__global__ void scan_kernel() {
    __shared__ unsigned long long w0[32], w1[32];
    const int tid = threadIdx.x;
    const int lane = tid & 31, wid = tid >> 5;

    const int base = tid * 8;
    int eidx[8];
    unsigned long long c0 = 0ULL, c1 = 0ULL;
#pragma unroll
    for (int j = 0; j < 8; j++) {
        int e = g_expert_idx[base + j];
        eidx[j] = e;
        if (e < 4) c0 += 1ULL << (16 * e);
        else       c1 += 1ULL << (16 * (e - 4));
    }
    unsigned long long s0 = c0, s1 = c1;
#pragma unroll
    for (int d = 1; d < 32; d <<= 1) {
        unsigned long long t0 = __shfl_up_sync(0xffffffffu, s0, d);
        unsigned long long t1 = __shfl_up_sync(0xffffffffu, s1, d);
        if (lane >= d) { s0 += t0; s1 += t1; }
    }
    if (lane == 31) { w0[wid] = s0; w1[wid] = s1; }

    for (int i = tid; i < E * CAP; i += 1024) g_slot_token[i] = -1;
    __syncthreads();
    if (wid == 0) {
        unsigned long long v0 = w0[lane], v1 = w1[lane];
#pragma unroll
        for (int d = 1; d < 32; d <<= 1) {
            unsigned long long t0 = __shfl_up_sync(0xffffffffu, v0, d);
            unsigned long long t1 = __shfl_up_sync(0xffffffffu, v1, d);
            if (lane >= d) { v0 += t0; v1 += t1; }
        }
        w0[lane] = v0; w1[lane] = v1;
    }
    __syncthreads();
    unsigned long long o0 = s0 - c0 + (wid > 0 ? w0[wid - 1] : 0ULL);
    unsigned long long o1 = s1 - c1 + (wid > 0 ? w1[wid - 1] : 0ULL);

    int off[E];
#pragma unroll
    for (int e = 0; e < 4; e++) {
        off[e]     = (int)((o0 >> (16 * e)) & 0xFFFFULL);
        off[e + 4] = (int)((o1 >> (16 * e)) & 0xFFFFULL);
    }
#pragma unroll
    for (int j = 0; j < 8; j++) {
        int t = base + j;
        int e = eidx[j];
        int p = 0;
#pragma unroll
        for (int q = 0; q < E; q++)
            if (e == q) { p = off[q]; off[q] = p + 1; }
        if (p < CAP) g_slot_token[e * CAP + p] = t;
    }
}

// ---------------- kernel 3: zero output ----------------
__global__ void zero_kernel(float4* __restrict__ out) {
    size_t i = (size_t)blockIdx.x * blockDim.x + threadIdx.x;
    out[i] = make_float4(0.f, 0.f, 0.f, 0.f);
}

// ---------------- hi/lo bf16 split helpers ----------------
__device__ __forceinline__ void split8(const float4 a, const float4 b,
                                       uint4& hi, uint4& lo) {
    float v[8] = {a.x, a.y, a.z, a.w, b.x, b.y, b.z, b.w};
    __nv_bfloat16 h[8], l[8];
#pragma unroll
    for (int i = 0; i < 8; i++) {
        h[i] = __float2bfloat16(v[i]);
        l[i] = __float2bfloat16(v[i] - __bfloat162float(h[i]));
    }
    hi = *(uint4*)h;
    lo = *(uint4*)l;
}

// ---------------- kernel 4: convert W -> bf16 hi/lo ----------------
__global__ void convW_kernel(const float* __restrict__ W) {
    size_t i = ((size_t)blockIdx.x * blockDim.x + threadIdx.x) * 8;
    float4 a = *(const float4*)(W + i);
    float4 b = *(const float4*)(W + i + 4);
    uint4 hi, lo;
    split8(a, b, hi, lo);
    *(uint4*)(g_Whi + i) = hi;
    *(uint4*)(g_Wlo + i) = lo;
}

// ---------------- kernel 5: gather + convert x -> per-slot bf16 hi/lo ----------------
__global__ void convA_kernel(const float* __restrict__ x) {
    int r = blockIdx.x;
    int tok = g_slot_token[r];
    size_t base = (size_t)r * H + threadIdx.x * 8;
    if (tok < 0) {
        uint4 z = make_uint4(0, 0, 0, 0);
        *(uint4*)(g_Ahi + base) = z;
        *(uint4*)(g_Alo + base) = z;
        return;
    }
    const float* xr = x + (size_t)tok * H + threadIdx.x * 8;
    float4 a = *(const float4*)xr;
    float4 b = *(const float4*)(xr + 4);
    uint4 hi, lo;
    split8(a, b, hi, lo);
    *(uint4*)(g_Ahi + base) = hi;
    *(uint4*)(g_Alo + base) = lo;
}

// ---------------- kernel 6: GEMM, 512 threads, 3-stage cp.async, XOR swizzle ----------------
#define BM 128
#define BN 128
#define BK 64                      // bf16 per chunk = 128B rows
#define KITER (H / BK)             // 16
#define ROW_B 128                  // bytes per smem row
#define PLANE_B (BM * ROW_B)       // 16384
#define STAGE_B (4 * PLANE_B)      // 65536
#define NSTAGE 3
#define SMEM_TOK 512
#define GEMM_SMEM (SMEM_TOK + NSTAGE * STAGE_B)   // 197120

__device__ __forceinline__ uint32_t smem_u32(const void* p) {
    uint32_t a;
    asm("{ .reg .u64 t; cvta.to.shared.u64 t, %1; cvt.u32.u64 %0, t; }" : "=r"(a) : "l"(p));
    return a;
}
__device__ __forceinline__ void cpasync16(uint32_t dst, const void* src) {
    asm volatile("cp.async.cg.shared.global [%0], [%1], 16;" :: "r"(dst), "l"(src));
}
__device__ __forceinline__ void ldsm4(uint32_t& r0, uint32_t& r1, uint32_t& r2, uint32_t& r3,
                                      uint32_t addr) {
    asm volatile("ldmatrix.sync.aligned.m8n8.x4.shared.b16 {%0,%1,%2,%3}, [%4];"
                 : "=r"(r0), "=r"(r1), "=r"(r2), "=r"(r3) : "r"(addr));
}
__device__ __forceinline__ void mma16816(float* d, const uint32_t* a, uint32_t b0, uint32_t b1) {
    asm volatile("mma.sync.aligned.m16n8k16.row.col.f32.bf16.bf16.f32 "
                 "{%0,%1,%2,%3}, {%4,%5,%6,%7}, {%8,%9}, {%0,%1,%2,%3};"
                 : "+f"(d[0]), "+f"(d[1]), "+f"(d[2]), "+f"(d[3])
                 : "r"(a[0]), "r"(a[1]), "r"(a[2]), "r"(a[3]), "r"(b0), "r"(b1));
}

__global__ void __launch_bounds__(512, 1)
moe_gemm(const float* __restrict__ bias, float* __restrict__ out) {
    extern __shared__ char smem[];
    int* s_tok = (int*)smem;
    const uint32_t sbase = smem_u32(smem) + SMEM_TOK;

    const int tid  = threadIdx.x;
    const int lane = tid & 31;
    const int wid  = tid >> 5;             // 0..15, warp grid 4(M) x 4(N)
    const int bm = blockIdx.y * BM;
    const int bn = blockIdx.x * BN;
    const int e  = bm >> 10;

    if (tid < BM) s_tok[tid] = g_slot_token[bm + tid];

    // ---- cp.async mapping: row = tid>>2 (4 thr/row), 2 x 16B segs each ----
    const int crow = tid >> 2;
    const int s0   = (tid & 3) * 2;
    const uint32_t d0 = (uint32_t)(crow * ROW_B + ((s0     ^ (crow & 7)) * 16));
    const uint32_t d1 = (uint32_t)(crow * ROW_B + (((s0+1) ^ (crow & 7)) * 16));
    const __nv_bfloat16* pAhi = g_Ahi + (size_t)(bm + crow) * H + s0 * 8;
    const __nv_bfloat16* pAlo = g_Alo + (size_t)(bm + crow) * H + s0 * 8;
    const __nv_bfloat16* pBhi = g_Whi + ((size_t)e * H + bn + crow) * H + s0 * 8;
    const __nv_bfloat16* pBlo = g_Wlo + ((size_t)e * H + bn + crow) * H + s0 * 8;

#define ISSUE_STAGE(stg, kc) do { \
        uint32_t db = sbase + (stg) * STAGE_B; \
        int ko = (kc) * BK; \
        cpasync16(db + d0,               pAhi + ko); \
        cpasync16(db + d1,               pAhi + ko + 8); \
        cpasync16(db + PLANE_B + d0,     pAlo + ko); \
        cpasync16(db + PLANE_B + d1,     pAlo + ko + 8); \
        cpasync16(db + 2*PLANE_B + d0,   pBhi + ko); \
        cpasync16(db + 2*PLANE_B + d1,   pBhi + ko + 8); \
        cpasync16(db + 3*PLANE_B + d0,   pBlo + ko); \
        cpasync16(db + 3*PLANE_B + d1,   pBlo + ko + 8); \
        asm volatile("cp.async.commit_group;" ::: "memory"); \
    } while (0)

    float D[2][4][4];
#pragma unroll
    for (int mt = 0; mt < 2; mt++)
#pragma unroll
        for (int nt = 0; nt < 4; nt++)
#pragma unroll
            for (int r = 0; r < 4; r++) D[mt][nt][r] = 0.f;

    const int mrow = (wid >> 2) * 32 + (lane & 15);   // + mt*16
    const int nrow = (wid & 3) * 32 + (lane & 15);    // + np*16
    const int chalf = lane >> 4;                      // 16B half within k16

    ISSUE_STAGE(0, 0);
    ISSUE_STAGE(1, 1);

    for (int kc = 0; kc < KITER; kc++) {
        asm volatile("cp.async.wait_group 1;" ::: "memory");
        __syncthreads();

        const uint32_t ab = sbase + (kc % NSTAGE) * STAGE_B;
#pragma unroll
        for (int ks = 0; ks < 4; ks++) {
            const int seg = ks * 2 + chalf;
            uint32_t ahi[2][4], alo[2][4], bh[2][4], bl[2][4];
#pragma unroll
            for (int mt = 0; mt < 2; mt++) {
                int r = mrow + mt * 16;
                uint32_t ad = ab + r * ROW_B + ((seg ^ (r & 7)) * 16);
                ldsm4(ahi[mt][0], ahi[mt][1], ahi[mt][2], ahi[mt][3], ad);
                ldsm4(alo[mt][0], alo[mt][1], alo[mt][2], alo[mt][3], ad + PLANE_B);
            }
#pragma unroll
            for (int np = 0; np < 2; np++) {
                int r = nrow + np * 16;
                uint32_t bd = ab + 2 * PLANE_B + r * ROW_B + ((seg ^ (r & 7)) * 16);
                ldsm4(bh[np][0], bh[np][1], bh[np][2], bh[np][3], bd);
                ldsm4(bl[np][0], bl[np][1], bl[np][2], bl[np][3], bd + PLANE_B);
            }
#pragma unroll
            for (int mt = 0; mt < 2; mt++)
#pragma unroll
                for (int nt = 0; nt < 4; nt++) {
                    int np = nt >> 1, od = nt & 1;
                    mma16816(D[mt][nt], ahi[mt], bh[np][od], bh[np][2 + od]);
                    mma16816(D[mt][nt], ahi[mt], bl[np][od], bl[np][2 + od]);
                    mma16816(D[mt][nt], alo[mt], bh[np][od], bh[np][2 + od]);
                }
        }

        if (kc + 2 < KITER) ISSUE_STAGE((kc + 2) % NSTAGE, kc + 2);
    }

    // ---- epilogue: gate * (D + bias) scattered to token rows ----
    const int wm = (wid >> 2) * 32;
    const int wn = (wid & 3) * 32;
#pragma unroll
    for (int mt = 0; mt < 2; mt++) {
#pragma unroll
        for (int half = 0; half < 2; half++) {
            int r = wm + mt * 16 + (lane >> 2) + half * 8;
            int tok = s_tok[r];
            if (tok < 0) continue;
            float g = g_gate[tok];
            float* orow = out + (size_t)tok * H + bn + wn;
#pragma unroll
            for (int nt = 0; nt < 4; nt++) {
                int c = nt * 8 + (lane & 3) * 2;
                float2 bb = *(const float2*)(bias + (size_t)e * H + bn + wn + c);
                float2 v;
                v.x = g * (D[mt][nt][half * 2 + 0] + bb.x);
                v.y = g * (D[mt][nt][half * 2 + 1] + bb.y);
                *(float2*)(orow + c) = v;
            }
        }
    }
}

extern "C" void kernel_launch(void* const* d_in, const int* in_sizes, int n_in,
                              void* d_out, int out_size) {
    const float* x  = (const float*)d_in[0];   // [T, H]
    const float* wg = (const float*)d_in[1];   // [H, E]
    const float* W  = (const float*)d_in[2];   // [E, H, H]
    const float* b  = (const float*)d_in[3];   // [E, H]
    float* out = (float*)d_out;                // [T, H]

    cudaFuncSetAttribute(moe_gemm, cudaFuncAttributeMaxDynamicSharedMemorySize, GEMM_SMEM);

    route_kernel<<<T_TOK / 8, 256>>>(x, wg);
    scan_kernel<<<1, 1024>>>();
    convW_kernel<<<(E * H * H / 8) / 256, 256>>>(W);
    zero_kernel<<<(T_TOK * H / 4) / 256, 256>>>((float4*)out);
    convA_kernel<<<T_TOK, 128>>>(x);
    dim3 grid(H / BN, T_TOK / BM);             // (8, 64)
    moe_gemm<<<grid, 512, GEMM_SMEM>>>(b, out);
}